// round 7
// baseline (speedup 1.0000x reference)
#include <cuda_runtime.h>
#include <cuda_bf16.h>
#include <float.h>
#include <stdint.h>

#define B        16
#define H        320
#define W        320
#define HW       (H * W)
#define P        64
#define K_TOP    100
#define NB64     64         // coarse histogram bins over (0.5, 1.0)
#define NFINE    256        // sub-bins within the cutoff coarse bin
#define CAND_CAP 32768
#define SBUF     4096       // coarse survivors cap
#define TOPBUF   512        // refined survivors cap
#define TR       8          // rows per K1 block

// Output layout (float32, tuple order): coors | params | scores | mask
#define OFF_COORS  0
#define OFF_PARAMS 3200
#define OFF_SCORES 105600
#define OFF_MASK   107200

// Device scratch (zero-init at load; K2 re-zeros after use -> replay safe)
__device__ unsigned           g_cnt[B];
__device__ unsigned           g_hist64[B * NB64];
__device__ unsigned long long g_cand[B * CAND_CAP];

static __device__ __forceinline__ float fmax3(float a, float b, float c) {
    return fmaxf(fmaxf(a, b), c);
}
// coarse bin 0..63 over score bits in [0x3F000000, 0x3F800000)
static __device__ __forceinline__ unsigned bin64(unsigned bits) {
    unsigned bn = (bits - 0x3F000000u) >> 17;
    return bn > 63u ? 63u : bn;
}

// ---------------------------------------------------------------------------
// K1: tiled 3x3 peak NMS + block-aggregated candidates + coarse histogram.
// Grid (H/TR, B), 256 threads.
// ---------------------------------------------------------------------------
__global__ __launch_bounds__(256) void k1_peaks(const float* __restrict__ hms) {
    __shared__ float s_tile[(TR + 2) * W];
    __shared__ float s_cmax[TR * W];
    __shared__ unsigned long long s_buf[1024];
    __shared__ unsigned s_h64[NB64];
    __shared__ unsigned s_cnt, s_base;

    const int b   = blockIdx.y;
    const int y0  = blockIdx.x * TR;
    const int tid = threadIdx.x;
    const float* hb = hms + b * HW;

    if (tid == 0) s_cnt = 0;
    if (tid < NB64) s_h64[tid] = 0u;

    // ---- Load (TR+2) rows as float4; OOB rows = -inf ----
    #pragma unroll
    for (int u = 0; u < 4; u++) {
        int i = tid + u * 256;
        if (i < (TR + 2) * (W / 4)) {
            int r  = i / (W / 4);
            int gy = y0 - 1 + r;
            float4 v = make_float4(-FLT_MAX, -FLT_MAX, -FLT_MAX, -FLT_MAX);
            if (gy >= 0 && gy < H)
                v = ((const float4*)(hb + gy * W))[i - r * (W / 4)];
            ((float4*)s_tile)[i] = v;
        }
    }
    __syncthreads();

    // ---- Phase A: vertical 3-max (float4) ----
    #pragma unroll
    for (int u = 0; u < 3; u++) {
        int i = tid + u * 256;
        if (i < TR * (W / 4)) {
            int r  = i / (W / 4);
            int c4 = i - r * (W / 4);
            float4 a = ((const float4*)s_tile)[(r    ) * (W / 4) + c4];
            float4 m = ((const float4*)s_tile)[(r + 1) * (W / 4) + c4];
            float4 d = ((const float4*)s_tile)[(r + 2) * (W / 4) + c4];
            float4 o;
            o.x = fmax3(a.x, m.x, d.x);
            o.y = fmax3(a.y, m.y, d.y);
            o.z = fmax3(a.z, m.z, d.z);
            o.w = fmax3(a.w, m.w, d.w);
            ((float4*)s_cmax)[i] = o;
        }
    }
    __syncthreads();

    // ---- Phase B: horizontal 3-max, peak test, smem compaction + hist ----
    #pragma unroll
    for (int u = 0; u < 3; u++) {
        int i = tid + u * 256;
        if (i < TR * (W / 4)) {
            int r  = i / (W / 4);
            int c4 = i - r * (W / 4);
            int x0 = c4 * 4;
            float4 mid = ((const float4*)s_tile)[(r + 1) * (W / 4) + c4];
            float4 cm  = ((const float4*)s_cmax)[r * (W / 4) + c4];
            float lf = (c4 > 0)         ? s_cmax[r * W + x0 - 1] : cm.x;
            float rt = (c4 < W / 4 - 1) ? s_cmax[r * W + x0 + 4] : cm.w;

            float wm[4];
            wm[0] = fmax3(lf,   cm.x, cm.y);
            wm[1] = fmax3(cm.x, cm.y, cm.z);
            wm[2] = fmax3(cm.y, cm.z, cm.w);
            wm[3] = fmax3(cm.z, cm.w, rt);
            float mv[4] = {mid.x, mid.y, mid.z, mid.w};

            #pragma unroll
            for (int e = 0; e < 4; e++) {
                if (mv[e] > 0.5f && mv[e] >= wm[e]) {
                    unsigned bits = __float_as_uint(mv[e]);
                    atomicAdd(&s_h64[bin64(bits)], 1u);
                    unsigned pos = atomicAdd(&s_cnt, 1u);
                    if (pos < 1024) {
                        unsigned pixIdx = (unsigned)((y0 + r) * W + x0 + e);
                        s_buf[pos] = ((unsigned long long)bits << 32)
                                   | (unsigned)(~pixIdx);
                    }
                }
            }
        }
    }
    __syncthreads();

    // ---- Flush: one count atomic + <=64 hist atomics + coalesced keys ----
    unsigned n = s_cnt;
    if (n > 1024) n = 1024;
    if (tid == 0) s_base = atomicAdd(&g_cnt[b], n);
    if (tid < NB64 && s_h64[tid]) atomicAdd(&g_hist64[b * NB64 + tid], s_h64[tid]);
    __syncthreads();
    unsigned base = s_base;
    unsigned long long* dst = g_cand + (size_t)b * CAND_CAP;
    for (unsigned i = tid; i < n; i += 256) {
        unsigned o = base + i;
        if (o < CAND_CAP) dst[o] = s_buf[i];
    }
}

// ---------------------------------------------------------------------------
// K2: per batch — coarse cutoff, single filtered pass + fine refine,
// rank-count, outputs, gather, scratch reset. Grid B, 256 threads.
// ---------------------------------------------------------------------------
__global__ __launch_bounds__(256) void k2_select(const float* __restrict__ pms,
                                                 float* __restrict__ out) {
    __shared__ unsigned s_h[NB64], s_suf[NB64];
    __shared__ unsigned s_fine[NFINE], s_fsuf[NFINE];
    __shared__ unsigned long long s_cand[SBUF];
    __shared__ unsigned long long s_top[TOPBUF];
    __shared__ unsigned s_n, s_n2;
    __shared__ int s_c, s_cs;
    __shared__ float s_score[K_TOP];
    __shared__ int   s_y[K_TOP], s_x[K_TOP], s_valid[K_TOP];

    const int b   = blockIdx.x;
    const int tid = threadIdx.x;
    const unsigned long long* cand = g_cand + (size_t)b * CAND_CAP;

    if (tid < NB64)  s_h[tid] = g_hist64[b * NB64 + tid];
    if (tid < NFINE) s_fine[tid] = 0u;
    if (tid < K_TOP) { s_valid[tid] = 0; s_y[tid] = 0; s_x[tid] = 0; s_score[tid] = 0.f; }
    if (tid == 0) { s_n = 0; s_n2 = 0; s_c = 0; s_cs = 0; }
    unsigned cnt = g_cnt[b];
    if (cnt > CAND_CAP) cnt = CAND_CAP;
    // reset scratch for next replay
    if (tid < NB64) g_hist64[b * NB64 + tid] = 0u;
    if (tid == 0)   g_cnt[b] = 0u;
    __syncthreads();

    // ---- Coarse cutoff: parallel suffix sums over 64 bins ----
    if (tid < NB64) {
        unsigned suf = 0;
        for (int j = tid + 1; j < NB64; j++) suf += s_h[j];
        s_suf[tid] = suf;
        if (suf + s_h[tid] >= K_TOP) atomicMax(&s_c, tid);
    }
    __syncthreads();
    const int c = s_c;
    const unsigned suffixHigh = s_suf[c];               // count in bins > c (< K unless c==0 && total<K)
    const unsigned thrLow = 0x3F000000u + ((unsigned)c << 17);
    __syncthreads();

    // ---- Single global pass: store keys >= thrLow, fine-hist bin c ----
    for (unsigned base = 0; base < cnt; base += 256 * 16) {
        unsigned long long v[16];
        #pragma unroll
        for (int u = 0; u < 16; u++) {
            unsigned i = base + u * 256 + tid;
            v[u] = (i < cnt) ? cand[i] : 0ull;
        }
        #pragma unroll
        for (int u = 0; u < 16; u++) {
            unsigned bits = (unsigned)(v[u] >> 32);
            if (v[u] && bits >= thrLow) {
                unsigned pos = atomicAdd(&s_n, 1u);
                if (pos < SBUF) s_cand[pos] = v[u];
                if (bin64(bits) == (unsigned)c)
                    atomicAdd(&s_fine[(bits >> 9) & (NFINE - 1)], 1u);
            }
        }
    }
    __syncthreads();

    // ---- Fine cutoff within bin c: need m more keys from it ----
    unsigned total = suffixHigh + s_h[c];
    int m = (int)K_TOP - (int)suffixHigh;               // >= 1 when total >= K
    if (tid < NFINE) {
        unsigned fsuf = 0;
        for (int j = tid + 1; j < NFINE; j++) fsuf += s_fine[j];
        s_fsuf[tid] = fsuf;
        if ((int)(fsuf + s_fine[tid]) >= m) atomicMax(&s_cs, tid);
    }
    __syncthreads();
    const unsigned thrFine = (total < K_TOP)
        ? thrLow                                        // keep everything
        : 0x3F000000u + ((unsigned)c << 17) + ((unsigned)s_cs << 9);

    // ---- Compact survivors >= thrFine into s_top (smem only) ----
    unsigned n = s_n; if (n > SBUF) n = SBUF;
    for (unsigned i = tid; i < n; i += 256) {
        unsigned long long key = s_cand[i];
        if ((unsigned)(key >> 32) >= thrFine) {
            unsigned pos = atomicAdd(&s_n2, 1u);
            if (pos < TOPBUF) s_top[pos] = key;
        }
    }
    __syncthreads();

    // ---- Rank by counting (keys unique) ----
    unsigned n2 = s_n2; if (n2 > TOPBUF) n2 = TOPBUF;
    for (unsigned i = tid; i < n2; i += 256) {
        unsigned long long key = s_top[i];
        unsigned rank = 0;
        for (unsigned j = 0; j < n2; j++) rank += (s_top[j] > key);
        if (rank < K_TOP) {
            unsigned bits = (unsigned)(key >> 32);
            unsigned idx  = ~((unsigned)key);
            int yv = (int)(idx / W);
            int xv = (int)(idx - (unsigned)yv * W);
            s_score[rank] = __uint_as_float(bits);
            s_y[rank] = yv;
            s_x[rank] = xv;
            s_valid[rank] = 1;
        }
    }
    __syncthreads();

    // ---- coors / scores / mask ----
    if (tid < K_TOP) {
        int v = s_valid[tid];
        int bk = b * K_TOP + tid;
        out[OFF_COORS  + bk * 2 + 0] = (float)s_y[tid];
        out[OFF_COORS  + bk * 2 + 1] = (float)s_x[tid];
        out[OFF_SCORES + bk]         = v ? s_score[tid] : 0.0f;
        out[OFF_MASK   + bk]         = v ? 1.0f : 0.0f;
    }

    // ---- Params gather: 1600 float4 per batch, MLP-7 ----
    const float4* pms4 = (const float4*)pms;
    float4*       out4 = (float4*)(out + OFF_PARAMS);
    float4 vals[7];
    #pragma unroll
    for (int u = 0; u < 7; u++) {
        int e = tid + u * 256;
        vals[u] = make_float4(0.f, 0.f, 0.f, 0.f);
        if (e < K_TOP * (P / 4)) {
            int k = e >> 4;
            int cc = e & 15;
            if (s_valid[k]) {
                long long rowOff = ((long long)(b * H + s_y[k]) * W + s_x[k]) * (P / 4);
                vals[u] = pms4[rowOff + cc];
            }
        }
    }
    #pragma unroll
    for (int u = 0; u < 7; u++) {
        int e = tid + u * 256;
        if (e < K_TOP * (P / 4)) {
            int k = e >> 4;
            int cc = e & 15;
            out4[(long long)(b * K_TOP + k) * (P / 4) + cc] = vals[u];
        }
    }
}

// ---------------------------------------------------------------------------
extern "C" void kernel_launch(void* const* d_in, const int* in_sizes, int n_in,
                              void* d_out, int out_size) {
    const float* hms = (const float*)d_in[0];
    const float* pms = (const float*)d_in[1];
    float* out = (float*)d_out;

    dim3 g1(H / TR, B);
    k1_peaks<<<g1, 256>>>(hms);
    k2_select<<<B, 256>>>(pms, out);
}

// round 9
// speedup vs baseline: 1.3458x; 1.3458x over previous
#include <cuda_runtime.h>
#include <cuda_bf16.h>
#include <float.h>
#include <stdint.h>

#define B        16
#define H        320
#define W        320
#define HW       (H * W)
#define P        64
#define K_TOP    100
#define NBIN     256         // bins over (0.5, 1.0) by float-bit mantissa
#define SEGCAP   512         // per-(batch,bin) segment capacity
#define KEYCAP   1024        // K2 smem key cap (> K_TOP + SEGCAP)
#define LBUF     1024        // K1 per-block candidate cap
#define TR       10          // rows per K1 block (H % TR == 0)

// Output layout (float32, tuple order): coors | params | scores | mask
#define OFF_COORS  0
#define OFF_PARAMS 3200
#define OFF_SCORES 105600
#define OFF_MASK   107200

// Device scratch (zero-init at module load; K2 re-zeros counts -> replay safe)
__device__ unsigned           g_binc[B * NBIN];
__device__ unsigned long long g_seg[(size_t)B * NBIN * SEGCAP];   // 16.8 MB

static __device__ __forceinline__ float fmax3(float a, float b, float c) {
    return fmaxf(fmaxf(a, b), c);
}
// bin 0..255 over score bits in [0x3F000000, 0x3F800000)
static __device__ __forceinline__ unsigned binOf(unsigned bits) {
    unsigned bn = (bits - 0x3F000000u) >> 15;
    return bn > (NBIN - 1u) ? (NBIN - 1u) : bn;
}

// ---------------------------------------------------------------------------
// K1: tiled 3x3 peak NMS; candidates scattered into per-(batch,bin) segments.
// Grid (H/TR, B), 256 threads.
// ---------------------------------------------------------------------------
__global__ __launch_bounds__(256) void k1_peaks(const float* __restrict__ hms) {
    __shared__ float s_tile[(TR + 2) * W];        // 15.4 KB
    __shared__ float s_cmax[TR * W];              // 12.8 KB
    __shared__ unsigned long long s_buf[LBUF];    // 8 KB
    __shared__ unsigned s_hist[NBIN];             // per-bin local counts
    __shared__ unsigned s_gbase[NBIN];            // reserved global bases
    __shared__ unsigned s_loc[NBIN];              // scatter cursors
    __shared__ unsigned s_cnt;

    const int b   = blockIdx.y;
    const int y0  = blockIdx.x * TR;
    const int tid = threadIdx.x;
    const float* hb = hms + b * HW;

    if (tid == 0) s_cnt = 0;
    s_hist[tid] = 0u;                 // NBIN == blockDim

    // ---- Load (TR+2) rows as float4; OOB rows = -inf ----
    #pragma unroll
    for (int u = 0; u < 4; u++) {
        int i = tid + u * 256;
        if (i < (TR + 2) * (W / 4)) {
            int r  = i / (W / 4);
            int gy = y0 - 1 + r;
            float4 v = make_float4(-FLT_MAX, -FLT_MAX, -FLT_MAX, -FLT_MAX);
            if (gy >= 0 && gy < H)
                v = ((const float4*)(hb + gy * W))[i - r * (W / 4)];
            ((float4*)s_tile)[i] = v;
        }
    }
    __syncthreads();

    // ---- Phase A: vertical 3-max (float4) ----
    #pragma unroll
    for (int u = 0; u < 4; u++) {
        int i = tid + u * 256;
        if (i < TR * (W / 4)) {
            int r  = i / (W / 4);
            int c4 = i - r * (W / 4);
            float4 a = ((const float4*)s_tile)[(r    ) * (W / 4) + c4];
            float4 m = ((const float4*)s_tile)[(r + 1) * (W / 4) + c4];
            float4 d = ((const float4*)s_tile)[(r + 2) * (W / 4) + c4];
            float4 o;
            o.x = fmax3(a.x, m.x, d.x);
            o.y = fmax3(a.y, m.y, d.y);
            o.z = fmax3(a.z, m.z, d.z);
            o.w = fmax3(a.w, m.w, d.w);
            ((float4*)s_cmax)[i] = o;
        }
    }
    __syncthreads();

    // ---- Phase B: horizontal 3-max, peak test, smem compaction + hist ----
    #pragma unroll
    for (int u = 0; u < 4; u++) {
        int i = tid + u * 256;
        if (i < TR * (W / 4)) {
            int r  = i / (W / 4);
            int c4 = i - r * (W / 4);
            int x0 = c4 * 4;
            float4 mid = ((const float4*)s_tile)[(r + 1) * (W / 4) + c4];
            float4 cm  = ((const float4*)s_cmax)[r * (W / 4) + c4];
            float lf = (c4 > 0)         ? s_cmax[r * W + x0 - 1] : cm.x;
            float rt = (c4 < W / 4 - 1) ? s_cmax[r * W + x0 + 4] : cm.w;

            float wm[4];
            wm[0] = fmax3(lf,   cm.x, cm.y);
            wm[1] = fmax3(cm.x, cm.y, cm.z);
            wm[2] = fmax3(cm.y, cm.z, cm.w);
            wm[3] = fmax3(cm.z, cm.w, rt);
            float mv[4] = {mid.x, mid.y, mid.z, mid.w};

            #pragma unroll
            for (int e = 0; e < 4; e++) {
                if (mv[e] > 0.5f && mv[e] >= wm[e]) {
                    unsigned pos = atomicAdd(&s_cnt, 1u);
                    if (pos < LBUF) {
                        unsigned bits = __float_as_uint(mv[e]);
                        atomicAdd(&s_hist[binOf(bits)], 1u);
                        unsigned pixIdx = (unsigned)((y0 + r) * W + x0 + e);
                        s_buf[pos] = ((unsigned long long)bits << 32)
                                   | (unsigned)(~pixIdx);
                    }
                }
            }
        }
    }
    __syncthreads();

    // ---- Reserve per-bin global ranges (one atomic per non-empty bin) ----
    {
        unsigned h = s_hist[tid];
        s_gbase[tid] = h ? atomicAdd(&g_binc[b * NBIN + tid], h) : 0u;
        s_loc[tid] = 0u;
    }
    __syncthreads();

    // ---- Scatter keys into their bin segments ----
    unsigned n = s_cnt;
    if (n > LBUF) n = LBUF;
    for (unsigned i = tid; i < n; i += 256) {
        unsigned long long key = s_buf[i];
        unsigned bin  = binOf((unsigned)(key >> 32));
        unsigned slot = s_gbase[bin] + atomicAdd(&s_loc[bin], 1u);
        if (slot < SEGCAP)
            g_seg[(size_t)(b * NBIN + bin) * SEGCAP + slot] = key;
    }
}

// ---------------------------------------------------------------------------
// K2: per batch — bin counts, suffix cutoff, load only top bins (~300 keys),
// rank-count, outputs, gather, scratch reset. Grid B, 256 threads.
// ---------------------------------------------------------------------------
__global__ __launch_bounds__(256) void k2_select(const float* __restrict__ pms,
                                                 float* __restrict__ out) {
    __shared__ unsigned s_h[NBIN];
    __shared__ unsigned s_pre[NBIN];
    __shared__ unsigned s_ntot;
    __shared__ int s_c;
    __shared__ unsigned long long s_keys[KEYCAP];   // 8 KB
    __shared__ float s_score[K_TOP];
    __shared__ int   s_y[K_TOP], s_x[K_TOP], s_valid[K_TOP];

    const int b   = blockIdx.x;
    const int tid = threadIdx.x;

    {
        unsigned v = g_binc[b * NBIN + tid];
        g_binc[b * NBIN + tid] = 0u;                // reset for next replay
        s_h[tid] = v > SEGCAP ? (unsigned)SEGCAP : v;
    }
    if (tid < K_TOP) { s_valid[tid] = 0; s_y[tid] = 0; s_x[tid] = 0; s_score[tid] = 0.f; }
    if (tid == 0) { s_c = 0; s_ntot = 0; }
    __syncthreads();

    // ---- Cutoff bin c: largest bin with count(bins >= c) >= K ----
    {
        unsigned suf = 0;
        for (int j = tid + 1; j < NBIN; j++) suf += s_h[j];
        if (suf + s_h[tid] >= K_TOP) atomicMax(&s_c, tid);
    }
    __syncthreads();
    const int c = s_c;

    // ---- Prefix offsets over bins [c, NBIN-1] for contiguous packing ----
    {
        unsigned pre = 0;
        for (int j = c; j < tid; j++) pre += s_h[j];
        s_pre[tid] = (tid >= c) ? pre : 0u;
        if (tid == NBIN - 1) {
            unsigned t = pre + s_h[tid];
            s_ntot = t > KEYCAP ? (unsigned)KEYCAP : t;
        }
    }
    __syncthreads();
    const unsigned n = s_ntot;

    // ---- Load only keys from bins >= c (typically ~150-350 keys) ----
    for (unsigned i = tid; i < n; i += 256) {
        int bin = c;
        while (bin < NBIN - 1 && i >= s_pre[bin] + s_h[bin]) bin++;
        unsigned idx = i - s_pre[bin];
        s_keys[i] = g_seg[(size_t)(b * NBIN + bin) * SEGCAP + idx];
    }
    __syncthreads();

    // ---- Rank by counting (keys unique); fill top-K slots ----
    for (unsigned i = tid; i < n; i += 256) {
        unsigned long long key = s_keys[i];
        unsigned rank = 0;
        for (unsigned j = 0; j < n; j++) rank += (s_keys[j] > key);
        if (rank < K_TOP) {
            unsigned bits = (unsigned)(key >> 32);
            unsigned idx  = ~((unsigned)key);
            int yv = (int)(idx / W);
            int xv = (int)(idx - (unsigned)yv * W);
            s_score[rank] = __uint_as_float(bits);
            s_y[rank] = yv;
            s_x[rank] = xv;
            s_valid[rank] = 1;
        }
    }
    __syncthreads();

    // ---- coors / scores / mask ----
    if (tid < K_TOP) {
        int v = s_valid[tid];
        int bk = b * K_TOP + tid;
        out[OFF_COORS  + bk * 2 + 0] = (float)s_y[tid];
        out[OFF_COORS  + bk * 2 + 1] = (float)s_x[tid];
        out[OFF_SCORES + bk]         = v ? s_score[tid] : 0.0f;
        out[OFF_MASK   + bk]         = v ? 1.0f : 0.0f;
    }

    // ---- Params gather: 1600 float4 per batch, MLP-7 ----
    const float4* pms4 = (const float4*)pms;
    float4*       out4 = (float4*)(out + OFF_PARAMS);
    float4 vals[7];
    #pragma unroll
    for (int u = 0; u < 7; u++) {
        int e = tid + u * 256;
        vals[u] = make_float4(0.f, 0.f, 0.f, 0.f);
        if (e < K_TOP * (P / 4)) {
            int k  = e >> 4;
            int cc = e & 15;
            if (s_valid[k]) {
                long long rowOff = ((long long)(b * H + s_y[k]) * W + s_x[k]) * (P / 4);
                vals[u] = pms4[rowOff + cc];
            }
        }
    }
    #pragma unroll
    for (int u = 0; u < 7; u++) {
        int e = tid + u * 256;
        if (e < K_TOP * (P / 4)) {
            int k  = e >> 4;
            int cc = e & 15;
            out4[(long long)(b * K_TOP + k) * (P / 4) + cc] = vals[u];
        }
    }
}

// ---------------------------------------------------------------------------
extern "C" void kernel_launch(void* const* d_in, const int* in_sizes, int n_in,
                              void* d_out, int out_size) {
    const float* hms = (const float*)d_in[0];
    const float* pms = (const float*)d_in[1];
    float* out = (float*)d_out;

    dim3 g1(H / TR, B);
    k1_peaks<<<g1, 256>>>(hms);
    k2_select<<<B, 256>>>(pms, out);
}